// round 8
// baseline (speedup 1.0000x reference)
#include <cuda_runtime.h>

// ---------------------------------------------------------------------------
// PointNet segmentation forward.
// - context branch of MLP3 folded into per-batch bias (K=320 -> K=64)
// - GEMM inner loops use packed fma.rn.f32x2 (FFMA2): 2x FMA per issue slot
// ---------------------------------------------------------------------------

namespace {
constexpr int B_      = 8;
constexpr int NPTS    = 4096;
constexpr int TOT     = B_ * NPTS;     // 32768
constexpr int G_      = 16;
constexpr int CELLS   = G_ * G_ * G_;
}

// ----------------------------- f32x2 helpers --------------------------------
__device__ __forceinline__ void ffma2(unsigned long long& d,
                                      unsigned long long a,
                                      unsigned long long b) {
    asm("fma.rn.f32x2 %0, %1, %2, %0;" : "+l"(d) : "l"(a), "l"(b));
}
__device__ __forceinline__ unsigned long long pack2(float v) {
    unsigned long long r;
    asm("mov.b64 %0, {%1, %1};" : "=l"(r) : "f"(v));
    return r;
}
__device__ __forceinline__ float2 unpack2(unsigned long long v) {
    float2 f;
    asm("mov.b64 {%0, %1}, %2;" : "=f"(f.x), "=f"(f.y) : "l"(v));
    return f;
}

// ------------------------- device scratch buffers --------------------------
__device__ __align__(16) float g_bufA[TOT * 64];
__device__ __align__(16) float g_f1[TOT * 64];
__device__ __align__(16) float g_buf128[TOT * 128];
__device__ __align__(16) float g_t256[TOT * 256];
__device__ __align__(16) float g_logits[TOT * 8];
__device__ __align__(16) int   g_ctx[B_ * 256];
__device__ __align__(16) float g_base[B_ * 256];
__device__ int    g_cnt[B_ * CELLS];
__device__ int    g_start[B_ * CELLS];
__device__ int    g_fill[B_ * CELLS];
__device__ __align__(16) float4 g_psort[TOT];
__device__ int    g_pidx[TOT];

// ------------------------------ init ---------------------------------------
__global__ void zero_kernel() {
    int i = blockIdx.x * blockDim.x + threadIdx.x;
    if (i < B_ * CELLS) g_cnt[i] = 0;
    if (i < B_ * 256)   g_ctx[i] = 0;
}

// ------------------------- layer 1a: 9 -> 64 --------------------------------
__global__ __launch_bounds__(256) void l1a_kernel(
    const float* __restrict__ pos, const float* __restrict__ xf,
    const float* __restrict__ W, const float* __restrict__ bias)
{
    __shared__ __align__(16) float Ws[9 * 64];
    __shared__ __align__(16) float Bs[64];
    int t = threadIdx.x;
    for (int i = t; i < 576; i += 256) Ws[i] = W[i];
    if (t < 64) Bs[t] = bias[t];
    __syncthreads();

    int r = blockIdx.x * 256 + t;
    float in[9];
    in[0] = pos[r * 3 + 0]; in[1] = pos[r * 3 + 1]; in[2] = pos[r * 3 + 2];
#pragma unroll
    for (int k = 0; k < 6; k++) in[3 + k] = xf[r * 6 + k];

    const float4* W4 = reinterpret_cast<const float4*>(Ws);
    const float4* B4 = reinterpret_cast<const float4*>(Bs);
    float4* out4 = reinterpret_cast<float4*>(g_bufA) + r * 16;
#pragma unroll
    for (int jq = 0; jq < 16; jq++) {
        float4 acc = B4[jq];
#pragma unroll
        for (int k = 0; k < 9; k++) {
            float4 w = W4[k * 16 + jq];
            acc.x = fmaf(in[k], w.x, acc.x);
            acc.y = fmaf(in[k], w.y, acc.y);
            acc.z = fmaf(in[k], w.z, acc.z);
            acc.w = fmaf(in[k], w.w, acc.w);
        }
        acc.x = fmaxf(acc.x, 0.f); acc.y = fmaxf(acc.y, 0.f);
        acc.z = fmaxf(acc.z, 0.f); acc.w = fmaxf(acc.w, 0.f);
        out4[jq] = acc;
    }
}

// ---------------------- 128x64 SGEMM (small N layers), FFMA2 ----------------
template <int K>
__global__ __launch_bounds__(256) void gemm64_kernel(
    const float* __restrict__ A, const float* __restrict__ W,
    const float* __restrict__ bias, float* __restrict__ C, int Nfull)
{
    constexpr int BM = 128, BK = 16, BN = 64;
    __shared__ __align__(16) float As[BK][BM];
    __shared__ __align__(16) float Ws[BK][BN];

    int tid = threadIdx.x;
    int rowBase = blockIdx.x * BM;
    int colBase = blockIdx.y * BN;
    int tx = tid & 15;
    int ty = tid >> 4;

    unsigned long long acc2[8][2];
#pragma unroll
    for (int r = 0; r < 8; r++) { acc2[r][0] = 0ull; acc2[r][1] = 0ull; }

    int arow = tid >> 2;
    int akq  = (tid & 3) << 2;
    int wkr  = tid >> 4;
    int wcq  = (tid & 15) << 2;

    const float* Aptr0 = A + (size_t)(rowBase + arow) * K + akq;
    const float* Aptr1 = Aptr0 + (size_t)64 * K;
    const float* Wptr  = W + (size_t)wkr * Nfull + colBase + wcq;

    for (int k0 = 0; k0 < K; k0 += BK) {
        float4 a0 = *reinterpret_cast<const float4*>(Aptr0 + k0);
        float4 a1 = *reinterpret_cast<const float4*>(Aptr1 + k0);
        float4 wv = *reinterpret_cast<const float4*>(Wptr + (size_t)k0 * Nfull);
        __syncthreads();
        As[akq + 0][arow] = a0.x; As[akq + 1][arow] = a0.y;
        As[akq + 2][arow] = a0.z; As[akq + 3][arow] = a0.w;
        As[akq + 0][arow + 64] = a1.x; As[akq + 1][arow + 64] = a1.y;
        As[akq + 2][arow + 64] = a1.z; As[akq + 3][arow + 64] = a1.w;
        *reinterpret_cast<float4*>(&Ws[wkr][wcq]) = wv;
        __syncthreads();
#pragma unroll
        for (int kk = 0; kk < BK; kk++) {
            float4 aA = *reinterpret_cast<const float4*>(&As[kk][ty * 8]);
            float4 aB = *reinterpret_cast<const float4*>(&As[kk][ty * 8 + 4]);
            ulonglong2 w = *reinterpret_cast<const ulonglong2*>(&Ws[kk][tx * 4]);
            float av[8] = {aA.x, aA.y, aA.z, aA.w, aB.x, aB.y, aB.z, aB.w};
#pragma unroll
            for (int r = 0; r < 8; r++) {
                unsigned long long ap = pack2(av[r]);
                ffma2(acc2[r][0], ap, w.x);
                ffma2(acc2[r][1], ap, w.y);
            }
        }
    }

    float4 bv = *reinterpret_cast<const float4*>(bias + colBase + (tx << 2));
#pragma unroll
    for (int i = 0; i < 8; i++) {
        float2 c0 = unpack2(acc2[i][0]);
        float2 c1 = unpack2(acc2[i][1]);
        float4 v;
        v.x = fmaxf(c0.x + bv.x, 0.f); v.y = fmaxf(c0.y + bv.y, 0.f);
        v.z = fmaxf(c1.x + bv.z, 0.f); v.w = fmaxf(c1.y + bv.w, 0.f);
        *reinterpret_cast<float4*>(
            &C[(size_t)(rowBase + ty * 8 + i) * Nfull + colBase + (tx << 2)]) = v;
    }
}

// --------------- 128x128 double-buffered SGEMM (big layers), FFMA2 ----------
// micro-tile 8x8: rows {ty*4+i, 64+ty*4+i}, cols {tx*4+j, 64+tx*4+j}
template <int K, bool POOL, bool BBIAS>
__global__ __launch_bounds__(256) void gemm128_kernel(
    const float* __restrict__ A, const float* __restrict__ W,
    const float* __restrict__ bias, float* __restrict__ C,
    int Nfull, int* __restrict__ pool)
{
    constexpr int BK = 16;
    constexpr int NCH = K / BK;
    __shared__ __align__(16) float As[2][BK][128];
    __shared__ __align__(16) float Ws[2][BK][128];

    int tid = threadIdx.x;
    int rowBase = blockIdx.x * 128;
    int colBase = blockIdx.y * 128;
    int tx = tid & 15, ty = tid >> 4;

    int arow = tid >> 1;
    int akq  = (tid & 1) * 8;
    const float* Aptr = A + (size_t)(rowBase + arow) * K + akq;
    int wk0 = tid >> 5;
    int wc0 = (tid & 31) * 4;
    const float* Wp0 = W + (size_t)wk0 * Nfull + colBase + wc0;
    const float* Wp1 = Wp0 + (size_t)8 * Nfull;

    float4 a0 = *reinterpret_cast<const float4*>(Aptr);
    float4 a1 = *reinterpret_cast<const float4*>(Aptr + 4);
    float4 w0 = *reinterpret_cast<const float4*>(Wp0);
    float4 w1 = *reinterpret_cast<const float4*>(Wp1);
    {
        float va[8] = {a0.x, a0.y, a0.z, a0.w, a1.x, a1.y, a1.z, a1.w};
#pragma unroll
        for (int i = 0; i < 8; i++) As[0][akq + i][arow] = va[i];
        *reinterpret_cast<float4*>(&Ws[0][wk0][wc0]) = w0;
        *reinterpret_cast<float4*>(&Ws[0][wk0 + 8][wc0]) = w1;
    }
    __syncthreads();

    unsigned long long acc2[8][4];
#pragma unroll
    for (int r = 0; r < 8; r++)
#pragma unroll
        for (int c = 0; c < 4; c++) acc2[r][c] = 0ull;

    for (int ch = 0; ch < NCH; ch++) {
        int cur = ch & 1;
        if (ch + 1 < NCH) {
            int off = (ch + 1) * BK;
            a0 = *reinterpret_cast<const float4*>(Aptr + off);
            a1 = *reinterpret_cast<const float4*>(Aptr + off + 4);
            w0 = *reinterpret_cast<const float4*>(Wp0 + (size_t)off * Nfull);
            w1 = *reinterpret_cast<const float4*>(Wp1 + (size_t)off * Nfull);
        }
#pragma unroll
        for (int kk = 0; kk < BK; kk++) {
            float4 ar0 = *reinterpret_cast<const float4*>(&As[cur][kk][ty * 4]);
            float4 ar1 = *reinterpret_cast<const float4*>(&As[cur][kk][64 + ty * 4]);
            ulonglong2 wp0 = *reinterpret_cast<const ulonglong2*>(&Ws[cur][kk][tx * 4]);
            ulonglong2 wp1 = *reinterpret_cast<const ulonglong2*>(&Ws[cur][kk][64 + tx * 4]);
            float av[8] = {ar0.x, ar0.y, ar0.z, ar0.w, ar1.x, ar1.y, ar1.z, ar1.w};
#pragma unroll
            for (int r = 0; r < 8; r++) {
                unsigned long long ap = pack2(av[r]);
                ffma2(acc2[r][0], ap, wp0.x);
                ffma2(acc2[r][1], ap, wp0.y);
                ffma2(acc2[r][2], ap, wp1.x);
                ffma2(acc2[r][3], ap, wp1.y);
            }
        }
        if (ch + 1 < NCH) {
            int nxt = cur ^ 1;
            float va[8] = {a0.x, a0.y, a0.z, a0.w, a1.x, a1.y, a1.z, a1.w};
#pragma unroll
            for (int i = 0; i < 8; i++) As[nxt][akq + i][arow] = va[i];
            *reinterpret_cast<float4*>(&Ws[nxt][wk0][wc0]) = w0;
            *reinterpret_cast<float4*>(&Ws[nxt][wk0 + 8][wc0]) = w1;
            __syncthreads();
        }
    }

    const float* bp = BBIAS ? (bias + (size_t)(rowBase >> 12) * Nfull) : bias;
    float4 b0 = *reinterpret_cast<const float4*>(bp + colBase + tx * 4);
    float4 b1 = *reinterpret_cast<const float4*>(bp + colBase + 64 + tx * 4);
    float bb[8] = {b0.x, b0.y, b0.z, b0.w, b1.x, b1.y, b1.z, b1.w};

    if (POOL) {
        float mx[8] = {0.f, 0.f, 0.f, 0.f, 0.f, 0.f, 0.f, 0.f};
#pragma unroll
        for (int r = 0; r < 8; r++) {
            float2 c0 = unpack2(acc2[r][0]);
            float2 c1 = unpack2(acc2[r][1]);
            float2 c2 = unpack2(acc2[r][2]);
            float2 c3 = unpack2(acc2[r][3]);
            float vals[8] = {c0.x, c0.y, c1.x, c1.y, c2.x, c2.y, c3.x, c3.y};
#pragma unroll
            for (int c = 0; c < 8; c++)
                mx[c] = fmaxf(mx[c], fmaxf(vals[c] + bb[c], 0.f));
        }
        int b = rowBase >> 12;
#pragma unroll
        for (int c = 0; c < 8; c++) {
            int col = colBase + ((c < 4) ? (tx * 4 + c) : (64 + tx * 4 + c - 4));
            atomicMax(&pool[b * Nfull + col], __float_as_int(mx[c]));
        }
    } else {
#pragma unroll
        for (int r = 0; r < 8; r++) {
            int row = rowBase + ((r < 4) ? (ty * 4 + r) : (64 + ty * 4 + r - 4));
            float2 c0 = unpack2(acc2[r][0]);
            float2 c1 = unpack2(acc2[r][1]);
            float2 c2 = unpack2(acc2[r][2]);
            float2 c3 = unpack2(acc2[r][3]);
            float4 v0, v1;
            v0.x = fmaxf(c0.x + bb[0], 0.f);
            v0.y = fmaxf(c0.y + bb[1], 0.f);
            v0.z = fmaxf(c1.x + bb[2], 0.f);
            v0.w = fmaxf(c1.y + bb[3], 0.f);
            v1.x = fmaxf(c2.x + bb[4], 0.f);
            v1.y = fmaxf(c2.y + bb[5], 0.f);
            v1.z = fmaxf(c3.x + bb[6], 0.f);
            v1.w = fmaxf(c3.y + bb[7], 0.f);
            *reinterpret_cast<float4*>(&C[(size_t)row * Nfull + colBase + tx * 4]) = v0;
            *reinterpret_cast<float4*>(&C[(size_t)row * Nfull + colBase + 64 + tx * 4]) = v1;
        }
    }
}

// ----------- per-batch context bias: base = ctx @ W1[0:256,:] + b1 ----------
__global__ __launch_bounds__(256) void ctxbase_kernel(
    const float* __restrict__ W1, const float* __restrict__ b1)
{
    int b = blockIdx.x, j = threadIdx.x;
    __shared__ float cs[256];
    cs[j] = __int_as_float(g_ctx[b * 256 + j]);
    __syncthreads();
    float acc = b1[j];
#pragma unroll 8
    for (int k = 0; k < 256; k++)
        acc = fmaf(cs[k], W1[(size_t)k * 256 + j], acc);
    g_base[b * 256 + j] = acc;
}

// --------------------------- logits: 128 -> 7 -------------------------------
__global__ __launch_bounds__(256) void logits_kernel(
    const float* __restrict__ W, const float* __restrict__ bias)
{
    __shared__ __align__(16) float Ws[128 * 8];
    __shared__ __align__(16) float Bs[8];
    int t = threadIdx.x;
    for (int i = t; i < 1024; i += 256) {
        int k = i >> 3, j = i & 7;
        Ws[i] = (j < 7) ? W[k * 7 + j] : 0.f;
    }
    if (t < 8) Bs[t] = (t < 7) ? bias[t] : 0.f;
    __syncthreads();

    int r = blockIdx.x * 256 + t;
    float acc[8];
#pragma unroll
    for (int j = 0; j < 8; j++) acc[j] = Bs[j];

    const float4* A4 = reinterpret_cast<const float4*>(g_buf128) + r * 32;
#pragma unroll 4
    for (int kq = 0; kq < 32; kq++) {
        float4 a = A4[kq];
        float va[4] = {a.x, a.y, a.z, a.w};
#pragma unroll
        for (int e = 0; e < 4; e++) {
            const float4* w4 = reinterpret_cast<const float4*>(&Ws[(kq * 4 + e) * 8]);
            float4 w0 = w4[0], w1 = w4[1];
            float s = va[e];
            acc[0] = fmaf(s, w0.x, acc[0]); acc[1] = fmaf(s, w0.y, acc[1]);
            acc[2] = fmaf(s, w0.z, acc[2]); acc[3] = fmaf(s, w0.w, acc[3]);
            acc[4] = fmaf(s, w1.x, acc[4]); acc[5] = fmaf(s, w1.y, acc[5]);
            acc[6] = fmaf(s, w1.z, acc[6]); acc[7] = fmaf(s, w1.w, acc[7]);
        }
    }
    float4* out = reinterpret_cast<float4*>(g_logits) + r * 2;
    out[0] = make_float4(acc[0], acc[1], acc[2], acc[3]);
    out[1] = make_float4(acc[4], acc[5], acc[6], 0.f);
}

// ----------------------------- grid build -----------------------------------
__device__ __forceinline__ int cell_bin(float px, float py, float pz, int b) {
    int cx = min(max(__float2int_rz(px * 16.f), 0), 15);
    int cy = min(max(__float2int_rz(py * 16.f), 0), 15);
    int cz = min(max(__float2int_rz(pz * 16.f), 0), 15);
    return b * CELLS + ((cz << 8) + (cy << 4) + cx);
}

__global__ void hist_kernel(const float* __restrict__ pos) {
    int r = blockIdx.x * blockDim.x + threadIdx.x;
    if (r >= TOT) return;
    int b = r >> 12;
    atomicAdd(&g_cnt[cell_bin(pos[r * 3], pos[r * 3 + 1], pos[r * 3 + 2], b)], 1);
}

__global__ __launch_bounds__(256) void scan_kernel() {
    int b = blockIdx.x, t = threadIdx.x;
    __shared__ int part[256];
    int base = b * CELLS;
    int c[16]; int s = 0;
#pragma unroll
    for (int i = 0; i < 16; i++) { c[i] = g_cnt[base + t * 16 + i]; s += c[i]; }
    part[t] = s;
    __syncthreads();
    for (int off = 1; off < 256; off <<= 1) {
        int v = (t >= off) ? part[t - off] : 0;
        __syncthreads();
        part[t] += v;
        __syncthreads();
    }
    int run = base + part[t] - s;
#pragma unroll
    for (int i = 0; i < 16; i++) {
        int idx = base + t * 16 + i;
        g_start[idx] = run; g_fill[idx] = run;
        run += c[i];
    }
}

__global__ void scatter_kernel(const float* __restrict__ pos) {
    int r = blockIdx.x * blockDim.x + threadIdx.x;
    if (r >= TOT) return;
    int b = r >> 12;
    float px = pos[r * 3], py = pos[r * 3 + 1], pz = pos[r * 3 + 2];
    int bin = cell_bin(px, py, pz, b);
    int dst = atomicAdd(&g_fill[bin], 1);
    g_psort[dst] = make_float4(-2.f * px, -2.f * py, -2.f * pz,
                               px * px + py * py + pz * pz);
    g_pidx[dst] = r;
}

// ------------------------ knn (k=3) + interpolate ----------------------------
__global__ __launch_bounds__(256) void knn_kernel(
    const float* __restrict__ posy, float* __restrict__ out)
{
    int q = blockIdx.x * 256 + threadIdx.x;
    if (q >= TOT) return;
    int b = q >> 12;
    float qx = posy[q * 3], qy = posy[q * 3 + 1], qz = posy[q * 3 + 2];
    float ry = qx * qx + qy * qy + qz * qz;
    int cx = min(max(__float2int_rz(qx * 16.f), 0), 15);
    int cy = min(max(__float2int_rz(qy * 16.f), 0), 15);
    int cz = min(max(__float2int_rz(qz * 16.f), 0), 15);

    float bd0 = 3.4e38f, bd1 = 3.4e38f, bd2 = 3.4e38f;
    int bp0 = 0, bp1 = 0, bp2 = 0;
    const float h = 1.0f / 16.0f;
    int cbase = b * CELLS;

    auto visit = [&](int x, int y, int z) {
        int bin = cbase + ((z << 8) + (y << 4) + x);
        int s0 = g_start[bin];
        int e0 = s0 + g_cnt[bin];
        for (int j = s0; j < e0; j++) {
            float4 p = g_psort[j];
            float d = fmaf(p.x, qx, fmaf(p.y, qy, fmaf(p.z, qz, p.w)));
            if (d < bd2) {
                if (d < bd1) {
                    bd2 = bd1; bp2 = bp1;
                    if (d < bd0) { bd1 = bd0; bp1 = bp0; bd0 = d; bp0 = j; }
                    else         { bd1 = d;  bp1 = j; }
                } else { bd2 = d; bp2 = j; }
            }
        }
    };

    for (int r = 0; r < G_; r++) {
        int zlo = cz - r, zhi = cz + r;
        for (int z = max(zlo, 0); z <= min(zhi, 15); z++) {
            bool zf = (z == zlo) || (z == zhi);
            int ylo = cy - r, yhi = cy + r;
            for (int y = max(ylo, 0); y <= min(yhi, 15); y++) {
                bool yf = (y == ylo) || (y == yhi);
                int xlo = cx - r, xhi = cx + r;
                if (zf || yf) {
                    for (int x = max(xlo, 0); x <= min(xhi, 15); x++) visit(x, y, z);
                } else {
                    if (xlo >= 0) visit(xlo, y, z);
                    if (xhi <= 15 && xhi != xlo) visit(xhi, y, z);
                }
            }
        }
        if (bd2 < 3.0e38f) {
            float rb = (float)r * h;
            if (ry + bd2 <= rb * rb) break;
        }
    }

    float bds[3] = {bd0, bd1, bd2};
    int   bps[3] = {bp0, bp1, bp2};
    float a[7] = {0.f, 0.f, 0.f, 0.f, 0.f, 0.f, 0.f};
    float sw = 0.f;
#pragma unroll
    for (int k = 0; k < 3; k++) {
        float d2 = fmaxf(ry + bds[k], 1e-16f);
        float w = 1.0f / d2;
        sw += w;
        int idx = g_pidx[bps[k]];
        const float4* L = reinterpret_cast<const float4*>(g_logits + idx * 8);
        float4 l0 = L[0], l1 = L[1];
        a[0] = fmaf(w, l0.x, a[0]); a[1] = fmaf(w, l0.y, a[1]);
        a[2] = fmaf(w, l0.z, a[2]); a[3] = fmaf(w, l0.w, a[3]);
        a[4] = fmaf(w, l1.x, a[4]); a[5] = fmaf(w, l1.y, a[5]);
        a[6] = fmaf(w, l1.z, a[6]);
    }
    float inv = 1.0f / sw;
#pragma unroll
    for (int c = 0; c < 7; c++) out[q * 7 + c] = a[c] * inv;
}

// ------------------------------- launch --------------------------------------
extern "C" void kernel_launch(void* const* d_in, const int* in_sizes, int n_in,
                              void* d_out, int out_size)
{
    (void)in_sizes; (void)n_in; (void)out_size;
    const float* x    = (const float*)d_in[0];
    const float* pos  = (const float*)d_in[1];
    const float* posy = (const float*)d_in[2];
    const float* m1W2 = (const float*)d_in[7];  const float* m1b2 = (const float*)d_in[8];
    const float* m2W1 = (const float*)d_in[9];  const float* m2b1 = (const float*)d_in[10];
    const float* m2W2 = (const float*)d_in[11]; const float* m2b2 = (const float*)d_in[12];
    const float* m2W3 = (const float*)d_in[13]; const float* m2b3 = (const float*)d_in[14];
    const float* m3W1 = (const float*)d_in[15]; const float* m3b1 = (const float*)d_in[16];
    const float* m3W2 = (const float*)d_in[17]; const float* m3b2 = (const float*)d_in[18];
    const float* linW = (const float*)d_in[19]; const float* linb = (const float*)d_in[20];
    float* out = (float*)d_out;

    float *p_bufA, *p_f1, *p_buf128, *p_t256, *p_base;
    int* p_ctx;
    cudaGetSymbolAddress((void**)&p_bufA,   g_bufA);
    cudaGetSymbolAddress((void**)&p_f1,     g_f1);
    cudaGetSymbolAddress((void**)&p_buf128, g_buf128);
    cudaGetSymbolAddress((void**)&p_t256,   g_t256);
    cudaGetSymbolAddress((void**)&p_base,   g_base);
    cudaGetSymbolAddress((void**)&p_ctx,    g_ctx);

    zero_kernel<<<(B_ * CELLS + 255) / 256, 256>>>();

    // grid build (independent of MLP chain)
    hist_kernel<<<TOT / 256, 256>>>(pos);
    scan_kernel<<<B_, 256>>>();
    scatter_kernel<<<TOT / 256, 256>>>(pos);

    // MLP1: 9 -> 64 -> 64
    l1a_kernel<<<TOT / 256, 256>>>(pos, x, (const float*)d_in[5], (const float*)d_in[6]);
    gemm64_kernel<64><<<dim3(256, 1), 256>>>(p_bufA, m1W2, m1b2, p_f1, 64);

    // MLP2: 64 -> 64 -> 128 -> 256 (+ fused global max pool)
    gemm64_kernel<64><<<dim3(256, 1), 256>>>(p_f1, m2W1, m2b1, p_bufA, 64);
    gemm128_kernel<64, false, false><<<dim3(256, 1), 256>>>(
        p_bufA, m2W2, m2b2, p_buf128, 128, nullptr);
    gemm128_kernel<128, true, false><<<dim3(256, 2), 256>>>(
        p_buf128, m2W3, m2b3, nullptr, 256, p_ctx);

    // per-batch bias from context: base = ctx @ W1[0:256,:] + b1
    ctxbase_kernel<<<B_, 256>>>(m3W1, m3b1);

    // MLP3 layer1 (K reduced 320 -> 64): f3a = relu(f1 @ W1[256:,:] + base[batch])
    gemm128_kernel<64, false, true><<<dim3(256, 2), 256>>>(
        p_f1, m3W1 + 256 * 256, p_base, p_t256, 256, nullptr);
    // MLP3 layer2: 256 -> 128
    gemm128_kernel<256, false, false><<<dim3(256, 1), 256>>>(
        p_t256, m3W2, m3b2, p_buf128, 128, nullptr);

    logits_kernel<<<TOT / 256, 256>>>(linW, linb);

    knn_kernel<<<TOT / 256, 256>>>(posy, out);
}

// round 9
// speedup vs baseline: 1.0079x; 1.0079x over previous
#include <cuda_runtime.h>

// ---------------------------------------------------------------------------
// PointNet segmentation forward.
// - context branch of MLP3 folded into per-batch bias (K=320 -> K=64)
// - GEMM inner loops use packed fma.rn.f32x2 (FFMA2): 2x FMA per issue slot
// ---------------------------------------------------------------------------

namespace {
constexpr int B_      = 8;
constexpr int NPTS    = 4096;
constexpr int TOT     = B_ * NPTS;     // 32768
constexpr int G_      = 16;
constexpr int CELLS   = G_ * G_ * G_;
}

// ----------------------------- f32x2 helpers --------------------------------
__device__ __forceinline__ void ffma2(unsigned long long& d,
                                      unsigned long long a,
                                      unsigned long long b) {
    asm("fma.rn.f32x2 %0, %1, %2, %0;" : "+l"(d) : "l"(a), "l"(b));
}
__device__ __forceinline__ unsigned long long pack2(float v) {
    unsigned long long r;
    asm("mov.b64 %0, {%1, %1};" : "=l"(r) : "f"(v));
    return r;
}
__device__ __forceinline__ float2 unpack2(unsigned long long v) {
    float2 f;
    asm("mov.b64 {%0, %1}, %2;" : "=f"(f.x), "=f"(f.y) : "l"(v));
    return f;
}

// ------------------------- device scratch buffers --------------------------
__device__ __align__(16) float g_bufA[TOT * 64];
__device__ __align__(16) float g_f1[TOT * 64];
__device__ __align__(16) float g_buf128[TOT * 128];
__device__ __align__(16) float g_t256[TOT * 256];
__device__ __align__(16) float g_logits[TOT * 8];
__device__ __align__(16) int   g_ctx[B_ * 256];
__device__ __align__(16) float g_base[B_ * 256];
__device__ int    g_cnt[B_ * CELLS];
__device__ int    g_start[B_ * CELLS];
__device__ int    g_fill[B_ * CELLS];
__device__ __align__(16) float4 g_psort[TOT];
__device__ int    g_pidx[TOT];

// ------------------------------ init ---------------------------------------
__global__ void zero_kernel() {
    int i = blockIdx.x * blockDim.x + threadIdx.x;
    if (i < B_ * CELLS) g_cnt[i] = 0;
    if (i < B_ * 256)   g_ctx[i] = 0;
}

// ------------------------- layer 1a: 9 -> 64 --------------------------------
__global__ __launch_bounds__(256) void l1a_kernel(
    const float* __restrict__ pos, const float* __restrict__ xf,
    const float* __restrict__ W, const float* __restrict__ bias)
{
    __shared__ __align__(16) float Ws[9 * 64];
    __shared__ __align__(16) float Bs[64];
    int t = threadIdx.x;
    for (int i = t; i < 576; i += 256) Ws[i] = W[i];
    if (t < 64) Bs[t] = bias[t];
    __syncthreads();

    int r = blockIdx.x * 256 + t;
    float in[9];
    in[0] = pos[r * 3 + 0]; in[1] = pos[r * 3 + 1]; in[2] = pos[r * 3 + 2];
#pragma unroll
    for (int k = 0; k < 6; k++) in[3 + k] = xf[r * 6 + k];

    const float4* W4 = reinterpret_cast<const float4*>(Ws);
    const float4* B4 = reinterpret_cast<const float4*>(Bs);
    float4* out4 = reinterpret_cast<float4*>(g_bufA) + r * 16;
#pragma unroll
    for (int jq = 0; jq < 16; jq++) {
        float4 acc = B4[jq];
#pragma unroll
        for (int k = 0; k < 9; k++) {
            float4 w = W4[k * 16 + jq];
            acc.x = fmaf(in[k], w.x, acc.x);
            acc.y = fmaf(in[k], w.y, acc.y);
            acc.z = fmaf(in[k], w.z, acc.z);
            acc.w = fmaf(in[k], w.w, acc.w);
        }
        acc.x = fmaxf(acc.x, 0.f); acc.y = fmaxf(acc.y, 0.f);
        acc.z = fmaxf(acc.z, 0.f); acc.w = fmaxf(acc.w, 0.f);
        out4[jq] = acc;
    }
}

// ---------------------- 128x64 SGEMM (small N layers), FFMA2 ----------------
template <int K>
__global__ __launch_bounds__(256) void gemm64_kernel(
    const float* __restrict__ A, const float* __restrict__ W,
    const float* __restrict__ bias, float* __restrict__ C, int Nfull)
{
    constexpr int BM = 128, BK = 16, BN = 64;
    __shared__ __align__(16) float As[BK][BM];
    __shared__ __align__(16) float Ws[BK][BN];

    int tid = threadIdx.x;
    int rowBase = blockIdx.x * BM;
    int colBase = blockIdx.y * BN;
    int tx = tid & 15;
    int ty = tid >> 4;

    unsigned long long acc2[8][2];
#pragma unroll
    for (int r = 0; r < 8; r++) { acc2[r][0] = 0ull; acc2[r][1] = 0ull; }

    int arow = tid >> 2;
    int akq  = (tid & 3) << 2;
    int wkr  = tid >> 4;
    int wcq  = (tid & 15) << 2;

    const float* Aptr0 = A + (size_t)(rowBase + arow) * K + akq;
    const float* Aptr1 = Aptr0 + (size_t)64 * K;
    const float* Wptr  = W + (size_t)wkr * Nfull + colBase + wcq;

    for (int k0 = 0; k0 < K; k0 += BK) {
        float4 a0 = *reinterpret_cast<const float4*>(Aptr0 + k0);
        float4 a1 = *reinterpret_cast<const float4*>(Aptr1 + k0);
        float4 wv = *reinterpret_cast<const float4*>(Wptr + (size_t)k0 * Nfull);
        __syncthreads();
        As[akq + 0][arow] = a0.x; As[akq + 1][arow] = a0.y;
        As[akq + 2][arow] = a0.z; As[akq + 3][arow] = a0.w;
        As[akq + 0][arow + 64] = a1.x; As[akq + 1][arow + 64] = a1.y;
        As[akq + 2][arow + 64] = a1.z; As[akq + 3][arow + 64] = a1.w;
        *reinterpret_cast<float4*>(&Ws[wkr][wcq]) = wv;
        __syncthreads();
#pragma unroll
        for (int kk = 0; kk < BK; kk++) {
            float4 aA = *reinterpret_cast<const float4*>(&As[kk][ty * 8]);
            float4 aB = *reinterpret_cast<const float4*>(&As[kk][ty * 8 + 4]);
            ulonglong2 w = *reinterpret_cast<const ulonglong2*>(&Ws[kk][tx * 4]);
            float av[8] = {aA.x, aA.y, aA.z, aA.w, aB.x, aB.y, aB.z, aB.w};
#pragma unroll
            for (int r = 0; r < 8; r++) {
                unsigned long long ap = pack2(av[r]);
                ffma2(acc2[r][0], ap, w.x);
                ffma2(acc2[r][1], ap, w.y);
            }
        }
    }

    float4 bv = *reinterpret_cast<const float4*>(bias + colBase + (tx << 2));
#pragma unroll
    for (int i = 0; i < 8; i++) {
        float2 c0 = unpack2(acc2[i][0]);
        float2 c1 = unpack2(acc2[i][1]);
        float4 v;
        v.x = fmaxf(c0.x + bv.x, 0.f); v.y = fmaxf(c0.y + bv.y, 0.f);
        v.z = fmaxf(c1.x + bv.z, 0.f); v.w = fmaxf(c1.y + bv.w, 0.f);
        *reinterpret_cast<float4*>(
            &C[(size_t)(rowBase + ty * 8 + i) * Nfull + colBase + (tx << 2)]) = v;
    }
}

// --------------- 128x128 double-buffered SGEMM (big layers), FFMA2 ----------
// micro-tile 8x8: rows {ty*4+i, 64+ty*4+i}, cols {tx*4+j, 64+tx*4+j}
template <int K, bool POOL, bool BBIAS>
__global__ __launch_bounds__(256) void gemm128_kernel(
    const float* __restrict__ A, const float* __restrict__ W,
    const float* __restrict__ bias, float* __restrict__ C,
    int Nfull, int* __restrict__ pool)
{
    constexpr int BK = 16;
    constexpr int NCH = K / BK;
    __shared__ __align__(16) float As[2][BK][128];
    __shared__ __align__(16) float Ws[2][BK][128];

    int tid = threadIdx.x;
    int rowBase = blockIdx.x * 128;
    int colBase = blockIdx.y * 128;
    int tx = tid & 15, ty = tid >> 4;

    int arow = tid >> 1;
    int akq  = (tid & 1) * 8;
    const float* Aptr = A + (size_t)(rowBase + arow) * K + akq;
    int wk0 = tid >> 5;
    int wc0 = (tid & 31) * 4;
    const float* Wp0 = W + (size_t)wk0 * Nfull + colBase + wc0;
    const float* Wp1 = Wp0 + (size_t)8 * Nfull;

    float4 a0 = *reinterpret_cast<const float4*>(Aptr);
    float4 a1 = *reinterpret_cast<const float4*>(Aptr + 4);
    float4 w0 = *reinterpret_cast<const float4*>(Wp0);
    float4 w1 = *reinterpret_cast<const float4*>(Wp1);
    {
        float va[8] = {a0.x, a0.y, a0.z, a0.w, a1.x, a1.y, a1.z, a1.w};
#pragma unroll
        for (int i = 0; i < 8; i++) As[0][akq + i][arow] = va[i];
        *reinterpret_cast<float4*>(&Ws[0][wk0][wc0]) = w0;
        *reinterpret_cast<float4*>(&Ws[0][wk0 + 8][wc0]) = w1;
    }
    __syncthreads();

    unsigned long long acc2[8][4];
#pragma unroll
    for (int r = 0; r < 8; r++)
#pragma unroll
        for (int c = 0; c < 4; c++) acc2[r][c] = 0ull;

    for (int ch = 0; ch < NCH; ch++) {
        int cur = ch & 1;
        if (ch + 1 < NCH) {
            int off = (ch + 1) * BK;
            a0 = *reinterpret_cast<const float4*>(Aptr + off);
            a1 = *reinterpret_cast<const float4*>(Aptr + off + 4);
            w0 = *reinterpret_cast<const float4*>(Wp0 + (size_t)off * Nfull);
            w1 = *reinterpret_cast<const float4*>(Wp1 + (size_t)off * Nfull);
        }
#pragma unroll
        for (int kk = 0; kk < BK; kk++) {
            float4 ar0 = *reinterpret_cast<const float4*>(&As[cur][kk][ty * 4]);
            float4 ar1 = *reinterpret_cast<const float4*>(&As[cur][kk][64 + ty * 4]);
            ulonglong2 wp0 = *reinterpret_cast<const ulonglong2*>(&Ws[cur][kk][tx * 4]);
            ulonglong2 wp1 = *reinterpret_cast<const ulonglong2*>(&Ws[cur][kk][64 + tx * 4]);
            float av[8] = {ar0.x, ar0.y, ar0.z, ar0.w, ar1.x, ar1.y, ar1.z, ar1.w};
#pragma unroll
            for (int r = 0; r < 8; r++) {
                unsigned long long ap = pack2(av[r]);
                ffma2(acc2[r][0], ap, wp0.x);
                ffma2(acc2[r][1], ap, wp0.y);
                ffma2(acc2[r][2], ap, wp1.x);
                ffma2(acc2[r][3], ap, wp1.y);
            }
        }
        if (ch + 1 < NCH) {
            int nxt = cur ^ 1;
            float va[8] = {a0.x, a0.y, a0.z, a0.w, a1.x, a1.y, a1.z, a1.w};
#pragma unroll
            for (int i = 0; i < 8; i++) As[nxt][akq + i][arow] = va[i];
            *reinterpret_cast<float4*>(&Ws[nxt][wk0][wc0]) = w0;
            *reinterpret_cast<float4*>(&Ws[nxt][wk0 + 8][wc0]) = w1;
            __syncthreads();
        }
    }

    const float* bp = BBIAS ? (bias + (size_t)(rowBase >> 12) * Nfull) : bias;
    float4 b0 = *reinterpret_cast<const float4*>(bp + colBase + tx * 4);
    float4 b1 = *reinterpret_cast<const float4*>(bp + colBase + 64 + tx * 4);
    float bb[8] = {b0.x, b0.y, b0.z, b0.w, b1.x, b1.y, b1.z, b1.w};

    if (POOL) {
        float mx[8] = {0.f, 0.f, 0.f, 0.f, 0.f, 0.f, 0.f, 0.f};
#pragma unroll
        for (int r = 0; r < 8; r++) {
            float2 c0 = unpack2(acc2[r][0]);
            float2 c1 = unpack2(acc2[r][1]);
            float2 c2 = unpack2(acc2[r][2]);
            float2 c3 = unpack2(acc2[r][3]);
            float vals[8] = {c0.x, c0.y, c1.x, c1.y, c2.x, c2.y, c3.x, c3.y};
#pragma unroll
            for (int c = 0; c < 8; c++)
                mx[c] = fmaxf(mx[c], fmaxf(vals[c] + bb[c], 0.f));
        }
        int b = rowBase >> 12;
#pragma unroll
        for (int c = 0; c < 8; c++) {
            int col = colBase + ((c < 4) ? (tx * 4 + c) : (64 + tx * 4 + c - 4));
            atomicMax(&pool[b * Nfull + col], __float_as_int(mx[c]));
        }
    } else {
#pragma unroll
        for (int r = 0; r < 8; r++) {
            int row = rowBase + ((r < 4) ? (ty * 4 + r) : (64 + ty * 4 + r - 4));
            float2 c0 = unpack2(acc2[r][0]);
            float2 c1 = unpack2(acc2[r][1]);
            float2 c2 = unpack2(acc2[r][2]);
            float2 c3 = unpack2(acc2[r][3]);
            float4 v0, v1;
            v0.x = fmaxf(c0.x + bb[0], 0.f);
            v0.y = fmaxf(c0.y + bb[1], 0.f);
            v0.z = fmaxf(c1.x + bb[2], 0.f);
            v0.w = fmaxf(c1.y + bb[3], 0.f);
            v1.x = fmaxf(c2.x + bb[4], 0.f);
            v1.y = fmaxf(c2.y + bb[5], 0.f);
            v1.z = fmaxf(c3.x + bb[6], 0.f);
            v1.w = fmaxf(c3.y + bb[7], 0.f);
            *reinterpret_cast<float4*>(&C[(size_t)row * Nfull + colBase + tx * 4]) = v0;
            *reinterpret_cast<float4*>(&C[(size_t)row * Nfull + colBase + 64 + tx * 4]) = v1;
        }
    }
}

// ----------- per-batch context bias: base = ctx @ W1[0:256,:] + b1 ----------
__global__ __launch_bounds__(256) void ctxbase_kernel(
    const float* __restrict__ W1, const float* __restrict__ b1)
{
    int b = blockIdx.x, j = threadIdx.x;
    __shared__ float cs[256];
    cs[j] = __int_as_float(g_ctx[b * 256 + j]);
    __syncthreads();
    float acc = b1[j];
#pragma unroll 8
    for (int k = 0; k < 256; k++)
        acc = fmaf(cs[k], W1[(size_t)k * 256 + j], acc);
    g_base[b * 256 + j] = acc;
}

// --------------------------- logits: 128 -> 7 -------------------------------
__global__ __launch_bounds__(256) void logits_kernel(
    const float* __restrict__ W, const float* __restrict__ bias)
{
    __shared__ __align__(16) float Ws[128 * 8];
    __shared__ __align__(16) float Bs[8];
    int t = threadIdx.x;
    for (int i = t; i < 1024; i += 256) {
        int k = i >> 3, j = i & 7;
        Ws[i] = (j < 7) ? W[k * 7 + j] : 0.f;
    }
    if (t < 8) Bs[t] = (t < 7) ? bias[t] : 0.f;
    __syncthreads();

    int r = blockIdx.x * 256 + t;
    float acc[8];
#pragma unroll
    for (int j = 0; j < 8; j++) acc[j] = Bs[j];

    const float4* A4 = reinterpret_cast<const float4*>(g_buf128) + r * 32;
#pragma unroll 4
    for (int kq = 0; kq < 32; kq++) {
        float4 a = A4[kq];
        float va[4] = {a.x, a.y, a.z, a.w};
#pragma unroll
        for (int e = 0; e < 4; e++) {
            const float4* w4 = reinterpret_cast<const float4*>(&Ws[(kq * 4 + e) * 8]);
            float4 w0 = w4[0], w1 = w4[1];
            float s = va[e];
            acc[0] = fmaf(s, w0.x, acc[0]); acc[1] = fmaf(s, w0.y, acc[1]);
            acc[2] = fmaf(s, w0.z, acc[2]); acc[3] = fmaf(s, w0.w, acc[3]);
            acc[4] = fmaf(s, w1.x, acc[4]); acc[5] = fmaf(s, w1.y, acc[5]);
            acc[6] = fmaf(s, w1.z, acc[6]); acc[7] = fmaf(s, w1.w, acc[7]);
        }
    }
    float4* out = reinterpret_cast<float4*>(g_logits) + r * 2;
    out[0] = make_float4(acc[0], acc[1], acc[2], acc[3]);
    out[1] = make_float4(acc[4], acc[5], acc[6], 0.f);
}

// ----------------------------- grid build -----------------------------------
__device__ __forceinline__ int cell_bin(float px, float py, float pz, int b) {
    int cx = min(max(__float2int_rz(px * 16.f), 0), 15);
    int cy = min(max(__float2int_rz(py * 16.f), 0), 15);
    int cz = min(max(__float2int_rz(pz * 16.f), 0), 15);
    return b * CELLS + ((cz << 8) + (cy << 4) + cx);
}

__global__ void hist_kernel(const float* __restrict__ pos) {
    int r = blockIdx.x * blockDim.x + threadIdx.x;
    if (r >= TOT) return;
    int b = r >> 12;
    atomicAdd(&g_cnt[cell_bin(pos[r * 3], pos[r * 3 + 1], pos[r * 3 + 2], b)], 1);
}

__global__ __launch_bounds__(256) void scan_kernel() {
    int b = blockIdx.x, t = threadIdx.x;
    __shared__ int part[256];
    int base = b * CELLS;
    int c[16]; int s = 0;
#pragma unroll
    for (int i = 0; i < 16; i++) { c[i] = g_cnt[base + t * 16 + i]; s += c[i]; }
    part[t] = s;
    __syncthreads();
    for (int off = 1; off < 256; off <<= 1) {
        int v = (t >= off) ? part[t - off] : 0;
        __syncthreads();
        part[t] += v;
        __syncthreads();
    }
    int run = base + part[t] - s;
#pragma unroll
    for (int i = 0; i < 16; i++) {
        int idx = base + t * 16 + i;
        g_start[idx] = run; g_fill[idx] = run;
        run += c[i];
    }
}

__global__ void scatter_kernel(const float* __restrict__ pos) {
    int r = blockIdx.x * blockDim.x + threadIdx.x;
    if (r >= TOT) return;
    int b = r >> 12;
    float px = pos[r * 3], py = pos[r * 3 + 1], pz = pos[r * 3 + 2];
    int bin = cell_bin(px, py, pz, b);
    int dst = atomicAdd(&g_fill[bin], 1);
    g_psort[dst] = make_float4(-2.f * px, -2.f * py, -2.f * pz,
                               px * px + py * py + pz * pz);
    g_pidx[dst] = r;
}

// ------------------------ knn (k=3) + interpolate ----------------------------
__global__ __launch_bounds__(256) void knn_kernel(
    const float* __restrict__ posy, float* __restrict__ out)
{
    int q = blockIdx.x * 256 + threadIdx.x;
    if (q >= TOT) return;
    int b = q >> 12;
    float qx = posy[q * 3], qy = posy[q * 3 + 1], qz = posy[q * 3 + 2];
    float ry = qx * qx + qy * qy + qz * qz;
    int cx = min(max(__float2int_rz(qx * 16.f), 0), 15);
    int cy = min(max(__float2int_rz(qy * 16.f), 0), 15);
    int cz = min(max(__float2int_rz(qz * 16.f), 0), 15);

    float bd0 = 3.4e38f, bd1 = 3.4e38f, bd2 = 3.4e38f;
    int bp0 = 0, bp1 = 0, bp2 = 0;
    const float h = 1.0f / 16.0f;
    int cbase = b * CELLS;

    auto visit = [&](int x, int y, int z) {
        int bin = cbase + ((z << 8) + (y << 4) + x);
        int s0 = g_start[bin];
        int e0 = s0 + g_cnt[bin];
        for (int j = s0; j < e0; j++) {
            float4 p = g_psort[j];
            float d = fmaf(p.x, qx, fmaf(p.y, qy, fmaf(p.z, qz, p.w)));
            if (d < bd2) {
                if (d < bd1) {
                    bd2 = bd1; bp2 = bp1;
                    if (d < bd0) { bd1 = bd0; bp1 = bp0; bd0 = d; bp0 = j; }
                    else         { bd1 = d;  bp1 = j; }
                } else { bd2 = d; bp2 = j; }
            }
        }
    };

    for (int r = 0; r < G_; r++) {
        int zlo = cz - r, zhi = cz + r;
        for (int z = max(zlo, 0); z <= min(zhi, 15); z++) {
            bool zf = (z == zlo) || (z == zhi);
            int ylo = cy - r, yhi = cy + r;
            for (int y = max(ylo, 0); y <= min(yhi, 15); y++) {
                bool yf = (y == ylo) || (y == yhi);
                int xlo = cx - r, xhi = cx + r;
                if (zf || yf) {
                    for (int x = max(xlo, 0); x <= min(xhi, 15); x++) visit(x, y, z);
                } else {
                    if (xlo >= 0) visit(xlo, y, z);
                    if (xhi <= 15 && xhi != xlo) visit(xhi, y, z);
                }
            }
        }
        if (bd2 < 3.0e38f) {
            float rb = (float)r * h;
            if (ry + bd2 <= rb * rb) break;
        }
    }

    float bds[3] = {bd0, bd1, bd2};
    int   bps[3] = {bp0, bp1, bp2};
    float a[7] = {0.f, 0.f, 0.f, 0.f, 0.f, 0.f, 0.f};
    float sw = 0.f;
#pragma unroll
    for (int k = 0; k < 3; k++) {
        float d2 = fmaxf(ry + bds[k], 1e-16f);
        float w = 1.0f / d2;
        sw += w;
        int idx = g_pidx[bps[k]];
        const float4* L = reinterpret_cast<const float4*>(g_logits + idx * 8);
        float4 l0 = L[0], l1 = L[1];
        a[0] = fmaf(w, l0.x, a[0]); a[1] = fmaf(w, l0.y, a[1]);
        a[2] = fmaf(w, l0.z, a[2]); a[3] = fmaf(w, l0.w, a[3]);
        a[4] = fmaf(w, l1.x, a[4]); a[5] = fmaf(w, l1.y, a[5]);
        a[6] = fmaf(w, l1.z, a[6]);
    }
    float inv = 1.0f / sw;
#pragma unroll
    for (int c = 0; c < 7; c++) out[q * 7 + c] = a[c] * inv;
}

// ------------------------------- launch --------------------------------------
extern "C" void kernel_launch(void* const* d_in, const int* in_sizes, int n_in,
                              void* d_out, int out_size)
{
    (void)in_sizes; (void)n_in; (void)out_size;
    const float* x    = (const float*)d_in[0];
    const float* pos  = (const float*)d_in[1];
    const float* posy = (const float*)d_in[2];
    const float* m1W2 = (const float*)d_in[7];  const float* m1b2 = (const float*)d_in[8];
    const float* m2W1 = (const float*)d_in[9];  const float* m2b1 = (const float*)d_in[10];
    const float* m2W2 = (const float*)d_in[11]; const float* m2b2 = (const float*)d_in[12];
    const float* m2W3 = (const float*)d_in[13]; const float* m2b3 = (const float*)d_in[14];
    const float* m3W1 = (const float*)d_in[15]; const float* m3b1 = (const float*)d_in[16];
    const float* m3W2 = (const float*)d_in[17]; const float* m3b2 = (const float*)d_in[18];
    const float* linW = (const float*)d_in[19]; const float* linb = (const float*)d_in[20];
    float* out = (float*)d_out;

    float *p_bufA, *p_f1, *p_buf128, *p_t256, *p_base;
    int* p_ctx;
    cudaGetSymbolAddress((void**)&p_bufA,   g_bufA);
    cudaGetSymbolAddress((void**)&p_f1,     g_f1);
    cudaGetSymbolAddress((void**)&p_buf128, g_buf128);
    cudaGetSymbolAddress((void**)&p_t256,   g_t256);
    cudaGetSymbolAddress((void**)&p_base,   g_base);
    cudaGetSymbolAddress((void**)&p_ctx,    g_ctx);

    zero_kernel<<<(B_ * CELLS + 255) / 256, 256>>>();

    // grid build (independent of MLP chain)
    hist_kernel<<<TOT / 256, 256>>>(pos);
    scan_kernel<<<B_, 256>>>();
    scatter_kernel<<<TOT / 256, 256>>>(pos);

    // MLP1: 9 -> 64 -> 64
    l1a_kernel<<<TOT / 256, 256>>>(pos, x, (const float*)d_in[5], (const float*)d_in[6]);
    gemm64_kernel<64><<<dim3(256, 1), 256>>>(p_bufA, m1W2, m1b2, p_f1, 64);

    // MLP2: 64 -> 64 -> 128 -> 256 (+ fused global max pool)
    gemm64_kernel<64><<<dim3(256, 1), 256>>>(p_f1, m2W1, m2b1, p_bufA, 64);
    gemm128_kernel<64, false, false><<<dim3(256, 1), 256>>>(
        p_bufA, m2W2, m2b2, p_buf128, 128, nullptr);
    gemm128_kernel<128, true, false><<<dim3(256, 2), 256>>>(
        p_buf128, m2W3, m2b3, nullptr, 256, p_ctx);

    // per-batch bias from context: base = ctx @ W1[0:256,:] + b1
    ctxbase_kernel<<<B_, 256>>>(m3W1, m3b1);

    // MLP3 layer1 (K reduced 320 -> 64): f3a = relu(f1 @ W1[256:,:] + base[batch])
    gemm128_kernel<64, false, true><<<dim3(256, 2), 256>>>(
        p_f1, m3W1 + 256 * 256, p_base, p_t256, 256, nullptr);
    // MLP3 layer2: 256 -> 128
    gemm128_kernel<256, false, false><<<dim3(256, 1), 256>>>(
        p_t256, m3W2, m3b2, p_buf128, 128, nullptr);

    logits_kernel<<<TOT / 256, 256>>>(linW, linb);

    knn_kernel<<<TOT / 256, 256>>>(posy, out);
}

// round 10
// speedup vs baseline: 1.0080x; 1.0001x over previous
#include <cuda_runtime.h>

// ---------------------------------------------------------------------------
// PointNet segmentation forward.
// - context branch of MLP3 folded into per-batch bias (K=320 -> K=64)
// - GEMM inner loops use packed fma.rn.f32x2 (FFMA2): 2x FMA per issue slot
// ---------------------------------------------------------------------------

namespace {
constexpr int B_      = 8;
constexpr int NPTS    = 4096;
constexpr int TOT     = B_ * NPTS;     // 32768
constexpr int G_      = 16;
constexpr int CELLS   = G_ * G_ * G_;
}

// ----------------------------- f32x2 helpers --------------------------------
__device__ __forceinline__ void ffma2(unsigned long long& d,
                                      unsigned long long a,
                                      unsigned long long b) {
    asm("fma.rn.f32x2 %0, %1, %2, %0;" : "+l"(d) : "l"(a), "l"(b));
}
__device__ __forceinline__ unsigned long long pack2(float v) {
    unsigned long long r;
    asm("mov.b64 %0, {%1, %1};" : "=l"(r) : "f"(v));
    return r;
}
__device__ __forceinline__ float2 unpack2(unsigned long long v) {
    float2 f;
    asm("mov.b64 {%0, %1}, %2;" : "=f"(f.x), "=f"(f.y) : "l"(v));
    return f;
}

// ------------------------- device scratch buffers --------------------------
__device__ __align__(16) float g_bufA[TOT * 64];
__device__ __align__(16) float g_f1[TOT * 64];
__device__ __align__(16) float g_buf128[TOT * 128];
__device__ __align__(16) float g_t256[TOT * 256];
__device__ __align__(16) float g_logits[TOT * 8];
__device__ __align__(16) int   g_ctx[B_ * 256];
__device__ __align__(16) float g_base[B_ * 256];
__device__ int    g_cnt[B_ * CELLS];
__device__ int    g_start[B_ * CELLS];
__device__ int    g_fill[B_ * CELLS];
__device__ __align__(16) float4 g_psort[TOT];
__device__ int    g_pidx[TOT];

// ------------------------------ init ---------------------------------------
__global__ void zero_kernel() {
    int i = blockIdx.x * blockDim.x + threadIdx.x;
    if (i < B_ * CELLS) g_cnt[i] = 0;
    if (i < B_ * 256)   g_ctx[i] = 0;
}

// ------------------------- layer 1a: 9 -> 64 --------------------------------
__global__ __launch_bounds__(256) void l1a_kernel(
    const float* __restrict__ pos, const float* __restrict__ xf,
    const float* __restrict__ W, const float* __restrict__ bias)
{
    __shared__ __align__(16) float Ws[9 * 64];
    __shared__ __align__(16) float Bs[64];
    int t = threadIdx.x;
    for (int i = t; i < 576; i += 256) Ws[i] = W[i];
    if (t < 64) Bs[t] = bias[t];
    __syncthreads();

    int r = blockIdx.x * 256 + t;
    float in[9];
    in[0] = pos[r * 3 + 0]; in[1] = pos[r * 3 + 1]; in[2] = pos[r * 3 + 2];
#pragma unroll
    for (int k = 0; k < 6; k++) in[3 + k] = xf[r * 6 + k];

    const float4* W4 = reinterpret_cast<const float4*>(Ws);
    const float4* B4 = reinterpret_cast<const float4*>(Bs);
    float4* out4 = reinterpret_cast<float4*>(g_bufA) + r * 16;
#pragma unroll
    for (int jq = 0; jq < 16; jq++) {
        float4 acc = B4[jq];
#pragma unroll
        for (int k = 0; k < 9; k++) {
            float4 w = W4[k * 16 + jq];
            acc.x = fmaf(in[k], w.x, acc.x);
            acc.y = fmaf(in[k], w.y, acc.y);
            acc.z = fmaf(in[k], w.z, acc.z);
            acc.w = fmaf(in[k], w.w, acc.w);
        }
        acc.x = fmaxf(acc.x, 0.f); acc.y = fmaxf(acc.y, 0.f);
        acc.z = fmaxf(acc.z, 0.f); acc.w = fmaxf(acc.w, 0.f);
        out4[jq] = acc;
    }
}

// ---------------------- 128x64 SGEMM (small N layers), FFMA2 ----------------
template <int K>
__global__ __launch_bounds__(256) void gemm64_kernel(
    const float* __restrict__ A, const float* __restrict__ W,
    const float* __restrict__ bias, float* __restrict__ C, int Nfull)
{
    constexpr int BM = 128, BK = 16, BN = 64;
    __shared__ __align__(16) float As[BK][BM];
    __shared__ __align__(16) float Ws[BK][BN];

    int tid = threadIdx.x;
    int rowBase = blockIdx.x * BM;
    int colBase = blockIdx.y * BN;
    int tx = tid & 15;
    int ty = tid >> 4;

    unsigned long long acc2[8][2];
#pragma unroll
    for (int r = 0; r < 8; r++) { acc2[r][0] = 0ull; acc2[r][1] = 0ull; }

    int arow = tid >> 2;
    int akq  = (tid & 3) << 2;
    int wkr  = tid >> 4;
    int wcq  = (tid & 15) << 2;

    const float* Aptr0 = A + (size_t)(rowBase + arow) * K + akq;
    const float* Aptr1 = Aptr0 + (size_t)64 * K;
    const float* Wptr  = W + (size_t)wkr * Nfull + colBase + wcq;

    for (int k0 = 0; k0 < K; k0 += BK) {
        float4 a0 = *reinterpret_cast<const float4*>(Aptr0 + k0);
        float4 a1 = *reinterpret_cast<const float4*>(Aptr1 + k0);
        float4 wv = *reinterpret_cast<const float4*>(Wptr + (size_t)k0 * Nfull);
        __syncthreads();
        As[akq + 0][arow] = a0.x; As[akq + 1][arow] = a0.y;
        As[akq + 2][arow] = a0.z; As[akq + 3][arow] = a0.w;
        As[akq + 0][arow + 64] = a1.x; As[akq + 1][arow + 64] = a1.y;
        As[akq + 2][arow + 64] = a1.z; As[akq + 3][arow + 64] = a1.w;
        *reinterpret_cast<float4*>(&Ws[wkr][wcq]) = wv;
        __syncthreads();
#pragma unroll
        for (int kk = 0; kk < BK; kk++) {
            float4 aA = *reinterpret_cast<const float4*>(&As[kk][ty * 8]);
            float4 aB = *reinterpret_cast<const float4*>(&As[kk][ty * 8 + 4]);
            ulonglong2 w = *reinterpret_cast<const ulonglong2*>(&Ws[kk][tx * 4]);
            float av[8] = {aA.x, aA.y, aA.z, aA.w, aB.x, aB.y, aB.z, aB.w};
#pragma unroll
            for (int r = 0; r < 8; r++) {
                unsigned long long ap = pack2(av[r]);
                ffma2(acc2[r][0], ap, w.x);
                ffma2(acc2[r][1], ap, w.y);
            }
        }
    }

    float4 bv = *reinterpret_cast<const float4*>(bias + colBase + (tx << 2));
#pragma unroll
    for (int i = 0; i < 8; i++) {
        float2 c0 = unpack2(acc2[i][0]);
        float2 c1 = unpack2(acc2[i][1]);
        float4 v;
        v.x = fmaxf(c0.x + bv.x, 0.f); v.y = fmaxf(c0.y + bv.y, 0.f);
        v.z = fmaxf(c1.x + bv.z, 0.f); v.w = fmaxf(c1.y + bv.w, 0.f);
        *reinterpret_cast<float4*>(
            &C[(size_t)(rowBase + ty * 8 + i) * Nfull + colBase + (tx << 2)]) = v;
    }
}

// --------------- 128x128 double-buffered SGEMM (big layers), FFMA2 ----------
// micro-tile 8x8: rows {ty*4+i, 64+ty*4+i}, cols {tx*4+j, 64+tx*4+j}
template <int K, bool POOL, bool BBIAS>
__global__ __launch_bounds__(256) void gemm128_kernel(
    const float* __restrict__ A, const float* __restrict__ W,
    const float* __restrict__ bias, float* __restrict__ C,
    int Nfull, int* __restrict__ pool)
{
    constexpr int BK = 16;
    constexpr int NCH = K / BK;
    __shared__ __align__(16) float As[2][BK][128];
    __shared__ __align__(16) float Ws[2][BK][128];

    int tid = threadIdx.x;
    int rowBase = blockIdx.x * 128;
    int colBase = blockIdx.y * 128;
    int tx = tid & 15, ty = tid >> 4;

    int arow = tid >> 1;
    int akq  = (tid & 1) * 8;
    const float* Aptr = A + (size_t)(rowBase + arow) * K + akq;
    int wk0 = tid >> 5;
    int wc0 = (tid & 31) * 4;
    const float* Wp0 = W + (size_t)wk0 * Nfull + colBase + wc0;
    const float* Wp1 = Wp0 + (size_t)8 * Nfull;

    float4 a0 = *reinterpret_cast<const float4*>(Aptr);
    float4 a1 = *reinterpret_cast<const float4*>(Aptr + 4);
    float4 w0 = *reinterpret_cast<const float4*>(Wp0);
    float4 w1 = *reinterpret_cast<const float4*>(Wp1);
    {
        float va[8] = {a0.x, a0.y, a0.z, a0.w, a1.x, a1.y, a1.z, a1.w};
#pragma unroll
        for (int i = 0; i < 8; i++) As[0][akq + i][arow] = va[i];
        *reinterpret_cast<float4*>(&Ws[0][wk0][wc0]) = w0;
        *reinterpret_cast<float4*>(&Ws[0][wk0 + 8][wc0]) = w1;
    }
    __syncthreads();

    unsigned long long acc2[8][4];
#pragma unroll
    for (int r = 0; r < 8; r++)
#pragma unroll
        for (int c = 0; c < 4; c++) acc2[r][c] = 0ull;

    for (int ch = 0; ch < NCH; ch++) {
        int cur = ch & 1;
        if (ch + 1 < NCH) {
            int off = (ch + 1) * BK;
            a0 = *reinterpret_cast<const float4*>(Aptr + off);
            a1 = *reinterpret_cast<const float4*>(Aptr + off + 4);
            w0 = *reinterpret_cast<const float4*>(Wp0 + (size_t)off * Nfull);
            w1 = *reinterpret_cast<const float4*>(Wp1 + (size_t)off * Nfull);
        }
#pragma unroll
        for (int kk = 0; kk < BK; kk++) {
            float4 ar0 = *reinterpret_cast<const float4*>(&As[cur][kk][ty * 4]);
            float4 ar1 = *reinterpret_cast<const float4*>(&As[cur][kk][64 + ty * 4]);
            ulonglong2 wp0 = *reinterpret_cast<const ulonglong2*>(&Ws[cur][kk][tx * 4]);
            ulonglong2 wp1 = *reinterpret_cast<const ulonglong2*>(&Ws[cur][kk][64 + tx * 4]);
            float av[8] = {ar0.x, ar0.y, ar0.z, ar0.w, ar1.x, ar1.y, ar1.z, ar1.w};
#pragma unroll
            for (int r = 0; r < 8; r++) {
                unsigned long long ap = pack2(av[r]);
                ffma2(acc2[r][0], ap, wp0.x);
                ffma2(acc2[r][1], ap, wp0.y);
                ffma2(acc2[r][2], ap, wp1.x);
                ffma2(acc2[r][3], ap, wp1.y);
            }
        }
        if (ch + 1 < NCH) {
            int nxt = cur ^ 1;
            float va[8] = {a0.x, a0.y, a0.z, a0.w, a1.x, a1.y, a1.z, a1.w};
#pragma unroll
            for (int i = 0; i < 8; i++) As[nxt][akq + i][arow] = va[i];
            *reinterpret_cast<float4*>(&Ws[nxt][wk0][wc0]) = w0;
            *reinterpret_cast<float4*>(&Ws[nxt][wk0 + 8][wc0]) = w1;
            __syncthreads();
        }
    }

    const float* bp = BBIAS ? (bias + (size_t)(rowBase >> 12) * Nfull) : bias;
    float4 b0 = *reinterpret_cast<const float4*>(bp + colBase + tx * 4);
    float4 b1 = *reinterpret_cast<const float4*>(bp + colBase + 64 + tx * 4);
    float bb[8] = {b0.x, b0.y, b0.z, b0.w, b1.x, b1.y, b1.z, b1.w};

    if (POOL) {
        float mx[8] = {0.f, 0.f, 0.f, 0.f, 0.f, 0.f, 0.f, 0.f};
#pragma unroll
        for (int r = 0; r < 8; r++) {
            float2 c0 = unpack2(acc2[r][0]);
            float2 c1 = unpack2(acc2[r][1]);
            float2 c2 = unpack2(acc2[r][2]);
            float2 c3 = unpack2(acc2[r][3]);
            float vals[8] = {c0.x, c0.y, c1.x, c1.y, c2.x, c2.y, c3.x, c3.y};
#pragma unroll
            for (int c = 0; c < 8; c++)
                mx[c] = fmaxf(mx[c], fmaxf(vals[c] + bb[c], 0.f));
        }
        int b = rowBase >> 12;
#pragma unroll
        for (int c = 0; c < 8; c++) {
            int col = colBase + ((c < 4) ? (tx * 4 + c) : (64 + tx * 4 + c - 4));
            atomicMax(&pool[b * Nfull + col], __float_as_int(mx[c]));
        }
    } else {
#pragma unroll
        for (int r = 0; r < 8; r++) {
            int row = rowBase + ((r < 4) ? (ty * 4 + r) : (64 + ty * 4 + r - 4));
            float2 c0 = unpack2(acc2[r][0]);
            float2 c1 = unpack2(acc2[r][1]);
            float2 c2 = unpack2(acc2[r][2]);
            float2 c3 = unpack2(acc2[r][3]);
            float4 v0, v1;
            v0.x = fmaxf(c0.x + bb[0], 0.f);
            v0.y = fmaxf(c0.y + bb[1], 0.f);
            v0.z = fmaxf(c1.x + bb[2], 0.f);
            v0.w = fmaxf(c1.y + bb[3], 0.f);
            v1.x = fmaxf(c2.x + bb[4], 0.f);
            v1.y = fmaxf(c2.y + bb[5], 0.f);
            v1.z = fmaxf(c3.x + bb[6], 0.f);
            v1.w = fmaxf(c3.y + bb[7], 0.f);
            *reinterpret_cast<float4*>(&C[(size_t)row * Nfull + colBase + tx * 4]) = v0;
            *reinterpret_cast<float4*>(&C[(size_t)row * Nfull + colBase + 64 + tx * 4]) = v1;
        }
    }
}

// ----------- per-batch context bias: base = ctx @ W1[0:256,:] + b1 ----------
__global__ __launch_bounds__(256) void ctxbase_kernel(
    const float* __restrict__ W1, const float* __restrict__ b1)
{
    int b = blockIdx.x, j = threadIdx.x;
    __shared__ float cs[256];
    cs[j] = __int_as_float(g_ctx[b * 256 + j]);
    __syncthreads();
    float acc = b1[j];
#pragma unroll 8
    for (int k = 0; k < 256; k++)
        acc = fmaf(cs[k], W1[(size_t)k * 256 + j], acc);
    g_base[b * 256 + j] = acc;
}

// --------------------------- logits: 128 -> 7 -------------------------------
__global__ __launch_bounds__(256) void logits_kernel(
    const float* __restrict__ W, const float* __restrict__ bias)
{
    __shared__ __align__(16) float Ws[128 * 8];
    __shared__ __align__(16) float Bs[8];
    int t = threadIdx.x;
    for (int i = t; i < 1024; i += 256) {
        int k = i >> 3, j = i & 7;
        Ws[i] = (j < 7) ? W[k * 7 + j] : 0.f;
    }
    if (t < 8) Bs[t] = (t < 7) ? bias[t] : 0.f;
    __syncthreads();

    int r = blockIdx.x * 256 + t;
    float acc[8];
#pragma unroll
    for (int j = 0; j < 8; j++) acc[j] = Bs[j];

    const float4* A4 = reinterpret_cast<const float4*>(g_buf128) + r * 32;
#pragma unroll 4
    for (int kq = 0; kq < 32; kq++) {
        float4 a = A4[kq];
        float va[4] = {a.x, a.y, a.z, a.w};
#pragma unroll
        for (int e = 0; e < 4; e++) {
            const float4* w4 = reinterpret_cast<const float4*>(&Ws[(kq * 4 + e) * 8]);
            float4 w0 = w4[0], w1 = w4[1];
            float s = va[e];
            acc[0] = fmaf(s, w0.x, acc[0]); acc[1] = fmaf(s, w0.y, acc[1]);
            acc[2] = fmaf(s, w0.z, acc[2]); acc[3] = fmaf(s, w0.w, acc[3]);
            acc[4] = fmaf(s, w1.x, acc[4]); acc[5] = fmaf(s, w1.y, acc[5]);
            acc[6] = fmaf(s, w1.z, acc[6]); acc[7] = fmaf(s, w1.w, acc[7]);
        }
    }
    float4* out = reinterpret_cast<float4*>(g_logits) + r * 2;
    out[0] = make_float4(acc[0], acc[1], acc[2], acc[3]);
    out[1] = make_float4(acc[4], acc[5], acc[6], 0.f);
}

// ----------------------------- grid build -----------------------------------
__device__ __forceinline__ int cell_bin(float px, float py, float pz, int b) {
    int cx = min(max(__float2int_rz(px * 16.f), 0), 15);
    int cy = min(max(__float2int_rz(py * 16.f), 0), 15);
    int cz = min(max(__float2int_rz(pz * 16.f), 0), 15);
    return b * CELLS + ((cz << 8) + (cy << 4) + cx);
}

__global__ void hist_kernel(const float* __restrict__ pos) {
    int r = blockIdx.x * blockDim.x + threadIdx.x;
    if (r >= TOT) return;
    int b = r >> 12;
    atomicAdd(&g_cnt[cell_bin(pos[r * 3], pos[r * 3 + 1], pos[r * 3 + 2], b)], 1);
}

__global__ __launch_bounds__(256) void scan_kernel() {
    int b = blockIdx.x, t = threadIdx.x;
    __shared__ int part[256];
    int base = b * CELLS;
    int c[16]; int s = 0;
#pragma unroll
    for (int i = 0; i < 16; i++) { c[i] = g_cnt[base + t * 16 + i]; s += c[i]; }
    part[t] = s;
    __syncthreads();
    for (int off = 1; off < 256; off <<= 1) {
        int v = (t >= off) ? part[t - off] : 0;
        __syncthreads();
        part[t] += v;
        __syncthreads();
    }
    int run = base + part[t] - s;
#pragma unroll
    for (int i = 0; i < 16; i++) {
        int idx = base + t * 16 + i;
        g_start[idx] = run; g_fill[idx] = run;
        run += c[i];
    }
}

__global__ void scatter_kernel(const float* __restrict__ pos) {
    int r = blockIdx.x * blockDim.x + threadIdx.x;
    if (r >= TOT) return;
    int b = r >> 12;
    float px = pos[r * 3], py = pos[r * 3 + 1], pz = pos[r * 3 + 2];
    int bin = cell_bin(px, py, pz, b);
    int dst = atomicAdd(&g_fill[bin], 1);
    g_psort[dst] = make_float4(-2.f * px, -2.f * py, -2.f * pz,
                               px * px + py * py + pz * pz);
    g_pidx[dst] = r;
}

// ------------------------ knn (k=3) + interpolate ----------------------------
__global__ __launch_bounds__(256) void knn_kernel(
    const float* __restrict__ posy, float* __restrict__ out)
{
    int q = blockIdx.x * 256 + threadIdx.x;
    if (q >= TOT) return;
    int b = q >> 12;
    float qx = posy[q * 3], qy = posy[q * 3 + 1], qz = posy[q * 3 + 2];
    float ry = qx * qx + qy * qy + qz * qz;
    int cx = min(max(__float2int_rz(qx * 16.f), 0), 15);
    int cy = min(max(__float2int_rz(qy * 16.f), 0), 15);
    int cz = min(max(__float2int_rz(qz * 16.f), 0), 15);

    float bd0 = 3.4e38f, bd1 = 3.4e38f, bd2 = 3.4e38f;
    int bp0 = 0, bp1 = 0, bp2 = 0;
    const float h = 1.0f / 16.0f;
    int cbase = b * CELLS;

    auto visit = [&](int x, int y, int z) {
        int bin = cbase + ((z << 8) + (y << 4) + x);
        int s0 = g_start[bin];
        int e0 = s0 + g_cnt[bin];
        for (int j = s0; j < e0; j++) {
            float4 p = g_psort[j];
            float d = fmaf(p.x, qx, fmaf(p.y, qy, fmaf(p.z, qz, p.w)));
            if (d < bd2) {
                if (d < bd1) {
                    bd2 = bd1; bp2 = bp1;
                    if (d < bd0) { bd1 = bd0; bp1 = bp0; bd0 = d; bp0 = j; }
                    else         { bd1 = d;  bp1 = j; }
                } else { bd2 = d; bp2 = j; }
            }
        }
    };

    for (int r = 0; r < G_; r++) {
        int zlo = cz - r, zhi = cz + r;
        for (int z = max(zlo, 0); z <= min(zhi, 15); z++) {
            bool zf = (z == zlo) || (z == zhi);
            int ylo = cy - r, yhi = cy + r;
            for (int y = max(ylo, 0); y <= min(yhi, 15); y++) {
                bool yf = (y == ylo) || (y == yhi);
                int xlo = cx - r, xhi = cx + r;
                if (zf || yf) {
                    for (int x = max(xlo, 0); x <= min(xhi, 15); x++) visit(x, y, z);
                } else {
                    if (xlo >= 0) visit(xlo, y, z);
                    if (xhi <= 15 && xhi != xlo) visit(xhi, y, z);
                }
            }
        }
        if (bd2 < 3.0e38f) {
            float rb = (float)r * h;
            if (ry + bd2 <= rb * rb) break;
        }
    }

    float bds[3] = {bd0, bd1, bd2};
    int   bps[3] = {bp0, bp1, bp2};
    float a[7] = {0.f, 0.f, 0.f, 0.f, 0.f, 0.f, 0.f};
    float sw = 0.f;
#pragma unroll
    for (int k = 0; k < 3; k++) {
        float d2 = fmaxf(ry + bds[k], 1e-16f);
        float w = 1.0f / d2;
        sw += w;
        int idx = g_pidx[bps[k]];
        const float4* L = reinterpret_cast<const float4*>(g_logits + idx * 8);
        float4 l0 = L[0], l1 = L[1];
        a[0] = fmaf(w, l0.x, a[0]); a[1] = fmaf(w, l0.y, a[1]);
        a[2] = fmaf(w, l0.z, a[2]); a[3] = fmaf(w, l0.w, a[3]);
        a[4] = fmaf(w, l1.x, a[4]); a[5] = fmaf(w, l1.y, a[5]);
        a[6] = fmaf(w, l1.z, a[6]);
    }
    float inv = 1.0f / sw;
#pragma unroll
    for (int c = 0; c < 7; c++) out[q * 7 + c] = a[c] * inv;
}

// ------------------------------- launch --------------------------------------
extern "C" void kernel_launch(void* const* d_in, const int* in_sizes, int n_in,
                              void* d_out, int out_size)
{
    (void)in_sizes; (void)n_in; (void)out_size;
    const float* x    = (const float*)d_in[0];
    const float* pos  = (const float*)d_in[1];
    const float* posy = (const float*)d_in[2];
    const float* m1W2 = (const float*)d_in[7];  const float* m1b2 = (const float*)d_in[8];
    const float* m2W1 = (const float*)d_in[9];  const float* m2b1 = (const float*)d_in[10];
    const float* m2W2 = (const float*)d_in[11]; const float* m2b2 = (const float*)d_in[12];
    const float* m2W3 = (const float*)d_in[13]; const float* m2b3 = (const float*)d_in[14];
    const float* m3W1 = (const float*)d_in[15]; const float* m3b1 = (const float*)d_in[16];
    const float* m3W2 = (const float*)d_in[17]; const float* m3b2 = (const float*)d_in[18];
    const float* linW = (const float*)d_in[19]; const float* linb = (const float*)d_in[20];
    float* out = (float*)d_out;

    float *p_bufA, *p_f1, *p_buf128, *p_t256, *p_base;
    int* p_ctx;
    cudaGetSymbolAddress((void**)&p_bufA,   g_bufA);
    cudaGetSymbolAddress((void**)&p_f1,     g_f1);
    cudaGetSymbolAddress((void**)&p_buf128, g_buf128);
    cudaGetSymbolAddress((void**)&p_t256,   g_t256);
    cudaGetSymbolAddress((void**)&p_base,   g_base);
    cudaGetSymbolAddress((void**)&p_ctx,    g_ctx);

    zero_kernel<<<(B_ * CELLS + 255) / 256, 256>>>();

    // grid build (independent of MLP chain)
    hist_kernel<<<TOT / 256, 256>>>(pos);
    scan_kernel<<<B_, 256>>>();
    scatter_kernel<<<TOT / 256, 256>>>(pos);

    // MLP1: 9 -> 64 -> 64
    l1a_kernel<<<TOT / 256, 256>>>(pos, x, (const float*)d_in[5], (const float*)d_in[6]);
    gemm64_kernel<64><<<dim3(256, 1), 256>>>(p_bufA, m1W2, m1b2, p_f1, 64);

    // MLP2: 64 -> 64 -> 128 -> 256 (+ fused global max pool)
    gemm64_kernel<64><<<dim3(256, 1), 256>>>(p_f1, m2W1, m2b1, p_bufA, 64);
    gemm128_kernel<64, false, false><<<dim3(256, 1), 256>>>(
        p_bufA, m2W2, m2b2, p_buf128, 128, nullptr);
    gemm128_kernel<128, true, false><<<dim3(256, 2), 256>>>(
        p_buf128, m2W3, m2b3, nullptr, 256, p_ctx);

    // per-batch bias from context: base = ctx @ W1[0:256,:] + b1
    ctxbase_kernel<<<B_, 256>>>(m3W1, m3b1);

    // MLP3 layer1 (K reduced 320 -> 64): f3a = relu(f1 @ W1[256:,:] + base[batch])
    gemm128_kernel<64, false, true><<<dim3(256, 2), 256>>>(
        p_f1, m3W1 + 256 * 256, p_base, p_t256, 256, nullptr);
    // MLP3 layer2: 256 -> 128
    gemm128_kernel<256, false, false><<<dim3(256, 1), 256>>>(
        p_t256, m3W2, m3b2, p_buf128, 128, nullptr);

    logits_kernel<<<TOT / 256, 256>>>(linW, linb);

    knn_kernel<<<TOT / 256, 256>>>(posy, out);
}